// round 1
// baseline (speedup 1.0000x reference)
#include <cuda_runtime.h>
#include <cstdint>
#include <math.h>

// Problem constants
#define B_ 8
#define L_ 2048
#define D_ 1024
#define M_ (B_ * L_)   // 16384

// ---------------------------------------------------------------------------
// Scratch (static device globals — allocation-free per harness rules)
// ---------------------------------------------------------------------------
__device__ float g_qp[B_ * L_ * D_];   // 64 MB
__device__ float g_kp[B_ * L_ * D_];   // 64 MB
__device__ float g_vp[B_ * L_ * D_];   // 64 MB
__device__ float g_x [B_ * L_ * D_];   // 64 MB
__device__ float g_S [B_ * L_ * L_];   // 134 MB

// ---------------------------------------------------------------------------
// f32x2 packed-FMA helpers (FFMA2 — 2 FMAs per issue on sm_103a fma pipe)
// ---------------------------------------------------------------------------
__device__ __forceinline__ unsigned long long pack2(float x, float y) {
    unsigned long long r;
    asm("mov.b64 %0, {%1, %2};" : "=l"(r)
        : "r"(__float_as_uint(x)), "r"(__float_as_uint(y)));
    return r;
}
__device__ __forceinline__ unsigned long long ffma2(unsigned long long a,
                                                    unsigned long long b,
                                                    unsigned long long c) {
    unsigned long long d;
    asm("fma.rn.f32x2 %0, %1, %2, %3;" : "=l"(d) : "l"(a), "l"(b), "l"(c));
    return d;
}
__device__ __forceinline__ void unpack2(unsigned long long v, float& x, float& y) {
    unsigned int lo, hi;
    asm("mov.b64 {%0, %1}, %2;" : "=r"(lo), "=r"(hi) : "l"(v));
    x = __uint_as_float(lo);
    y = __uint_as_float(hi);
}

// ---------------------------------------------------------------------------
// Tiled GEMM: C[M,N] = epi( A @ B (+ optional transpose of B) )
//   TRANSB=false: B is [K,N] row-major.  TRANSB=true: B is [N,K] row-major.
//   CONCATA: A(m,k) = k < K/2 ? A[m,k] : A2[m, k-K/2]  (each half stride K/2)
//   EPI: 0 = +bias[n] (bias may be null)
//        1 = *alpha
//        2 = gate epilogue: out = x*mask*sigmoid(acc + bias) + q0
// Tile: 128x128x16, 256 threads, 8x8 microtile, double-buffered smem.
// All dims must be divisible by the tiles (they are for this problem).
// ---------------------------------------------------------------------------
template <bool TRANSB, int EPI, bool CONCATA>
__global__ __launch_bounds__(256)
void gemm_k(const float* __restrict__ A, const float* __restrict__ A2,
            const float* __restrict__ B, const float* __restrict__ bias,
            float* __restrict__ C,
            int M, int N, int K,
            long long sA, long long sB, long long sC,
            float alpha,
            const float* __restrict__ xbuf, const float* __restrict__ q0,
            const float* __restrict__ mask)
{
    constexpr int BM = 128, BN = 128, BK = 16, TM = 8, TN = 8;

    const int bn = blockIdx.x;
    const int bm = blockIdx.y;
    const int bz = blockIdx.z;
    A += (long long)bz * sA;
    B += (long long)bz * sB;
    C += (long long)bz * sC;

    __shared__ float As[2][BK][BM];
    __shared__ float Bs[2][BK][BN];

    const int tid = threadIdx.x;

    // loader mappings
    const int ldr = tid >> 2;          // 0..63 (row within 128-row tile, +64 for 2nd)
    const int ldc = (tid & 3) * 4;     // 0,4,8,12 (k within BK)
    const int brow = tid >> 5;         // 0..7   (k-row for NN B loads, +8 for 2nd)
    const int bcol = (tid & 31) * 4;   // 0..124 (n within BN)

    // compute mapping
    const int ty = tid >> 4;           // 0..15
    const int tx = tid & 15;           // 0..15
    const int mBase = ty * TM;
    const int nBase = tx * TN;

    float4 aReg[2], bReg[2];

    auto ldgA = [&](int kt) {
        long long kc = (long long)kt * BK + ldc;
        const float* Ap = A;
        int lda = K;
        if (CONCATA) {
            lda = K >> 1;
            if (kc >= lda) { Ap = A2; kc -= lda; }
        }
        const int r0 = bm * BM + ldr;
        aReg[0] = *(const float4*)(Ap + (long long)r0 * lda + kc);
        aReg[1] = *(const float4*)(Ap + (long long)(r0 + 64) * lda + kc);
    };
    auto stA = [&](int buf) {
        As[buf][ldc + 0][ldr] = aReg[0].x;
        As[buf][ldc + 1][ldr] = aReg[0].y;
        As[buf][ldc + 2][ldr] = aReg[0].z;
        As[buf][ldc + 3][ldr] = aReg[0].w;
        As[buf][ldc + 0][ldr + 64] = aReg[1].x;
        As[buf][ldc + 1][ldr + 64] = aReg[1].y;
        As[buf][ldc + 2][ldr + 64] = aReg[1].z;
        As[buf][ldc + 3][ldr + 64] = aReg[1].w;
    };
    auto ldgB = [&](int kt) {
        if (TRANSB) {
            const int n0 = bn * BN + ldr;
            long long kc = (long long)kt * BK + ldc;
            bReg[0] = *(const float4*)(B + (long long)n0 * K + kc);
            bReg[1] = *(const float4*)(B + (long long)(n0 + 64) * K + kc);
        } else {
            const int kr = kt * BK + brow;
            const int nc = bn * BN + bcol;
            bReg[0] = *(const float4*)(B + (long long)kr * N + nc);
            bReg[1] = *(const float4*)(B + (long long)(kr + 8) * N + nc);
        }
    };
    auto stB = [&](int buf) {
        if (TRANSB) {
            Bs[buf][ldc + 0][ldr] = bReg[0].x;
            Bs[buf][ldc + 1][ldr] = bReg[0].y;
            Bs[buf][ldc + 2][ldr] = bReg[0].z;
            Bs[buf][ldc + 3][ldr] = bReg[0].w;
            Bs[buf][ldc + 0][ldr + 64] = bReg[1].x;
            Bs[buf][ldc + 1][ldr + 64] = bReg[1].y;
            Bs[buf][ldc + 2][ldr + 64] = bReg[1].z;
            Bs[buf][ldc + 3][ldr + 64] = bReg[1].w;
        } else {
            *(float4*)&Bs[buf][brow][bcol]     = bReg[0];
            *(float4*)&Bs[buf][brow + 8][bcol] = bReg[1];
        }
    };

    unsigned long long acc[TM][TN / 2] = {};

    // prologue
    ldgA(0); ldgB(0);
    stA(0);  stB(0);
    __syncthreads();

    const int nt = K / BK;
    for (int t = 0; t < nt; ++t) {
        const int cur = t & 1;
        const bool more = (t + 1 < nt);
        if (more) { ldgA(t + 1); ldgB(t + 1); }

        #pragma unroll
        for (int k = 0; k < BK; ++k) {
            float4 a0 = *(const float4*)&As[cur][k][mBase];
            float4 a1 = *(const float4*)&As[cur][k][mBase + 4];
            float4 b0 = *(const float4*)&Bs[cur][k][nBase];
            float4 b1 = *(const float4*)&Bs[cur][k][nBase + 4];
            float av[8] = {a0.x, a0.y, a0.z, a0.w, a1.x, a1.y, a1.z, a1.w};
            unsigned long long bp[4] = {
                pack2(b0.x, b0.y), pack2(b0.z, b0.w),
                pack2(b1.x, b1.y), pack2(b1.z, b1.w)
            };
            #pragma unroll
            for (int m = 0; m < TM; ++m) {
                const unsigned long long ap = pack2(av[m], av[m]);
                #pragma unroll
                for (int n = 0; n < TN / 2; ++n)
                    acc[m][n] = ffma2(ap, bp[n], acc[m][n]);
            }
        }

        if (more) { stA(cur ^ 1); stB(cur ^ 1); __syncthreads(); }
    }

    // epilogue
    #pragma unroll
    for (int m = 0; m < TM; ++m) {
        const int row  = bm * BM + mBase + m;
        const int col0 = bn * BN + nBase;
        float vals[8];
        #pragma unroll
        for (int j = 0; j < 4; ++j)
            unpack2(acc[m][j], vals[2 * j], vals[2 * j + 1]);

        if (EPI == 0) {
            if (bias) {
                #pragma unroll
                for (int n = 0; n < 8; ++n) vals[n] += bias[col0 + n];
            }
        } else if (EPI == 1) {
            #pragma unroll
            for (int n = 0; n < 8; ++n) vals[n] *= alpha;
        } else {  // gate epilogue
            const float mv = mask[row];
            #pragma unroll
            for (int n = 0; n < 8; ++n) {
                const float g  = vals[n] + bias[col0 + n];
                const float sg = 1.0f / (1.0f + __expf(-g));
                const float xv = xbuf[(long long)row * N + col0 + n];
                const float qv = q0  [(long long)row * N + col0 + n];
                vals[n] = xv * mv * sg + qv;
            }
        }

        float4 o0 = make_float4(vals[0], vals[1], vals[2], vals[3]);
        float4 o1 = make_float4(vals[4], vals[5], vals[6], vals[7]);
        *(float4*)&C[(long long)row * N + col0]     = o0;
        *(float4*)&C[(long long)row * N + col0 + 4] = o1;
    }
}

// ---------------------------------------------------------------------------
// Row softmax over S (rows of length L_). One block per row.
// ---------------------------------------------------------------------------
__global__ __launch_bounds__(256)
void softmax_k(float* __restrict__ S)
{
    float* row = S + (long long)blockIdx.x * L_;
    const int tid = threadIdx.x;

    float v[8];
    #pragma unroll
    for (int i = 0; i < 8; ++i) v[i] = row[tid + 256 * i];

    float mx = v[0];
    #pragma unroll
    for (int i = 1; i < 8; ++i) mx = fmaxf(mx, v[i]);
    #pragma unroll
    for (int o = 16; o > 0; o >>= 1)
        mx = fmaxf(mx, __shfl_xor_sync(0xffffffffu, mx, o));

    __shared__ float red[8];
    if ((tid & 31) == 0) red[tid >> 5] = mx;
    __syncthreads();
    mx = red[0];
    #pragma unroll
    for (int i = 1; i < 8; ++i) mx = fmaxf(mx, red[i]);
    __syncthreads();  // before red reuse

    float s = 0.0f;
    #pragma unroll
    for (int i = 0; i < 8; ++i) { v[i] = __expf(v[i] - mx); s += v[i]; }
    #pragma unroll
    for (int o = 16; o > 0; o >>= 1)
        s += __shfl_xor_sync(0xffffffffu, s, o);
    if ((tid & 31) == 0) red[tid >> 5] = s;
    __syncthreads();
    s = 0.0f;
    #pragma unroll
    for (int i = 0; i < 8; ++i) s += red[i];

    const float inv = 1.0f / s;
    #pragma unroll
    for (int i = 0; i < 8; ++i) row[tid + 256 * i] = v[i] * inv;
}

// ---------------------------------------------------------------------------
// Host launch
// ---------------------------------------------------------------------------
extern "C" void kernel_launch(void* const* d_in, const int* in_sizes, int n_in,
                              void* d_out, int out_size)
{
    const float* q    = (const float*)d_in[0];
    const float* k    = (const float*)d_in[1];
    const float* v    = (const float*)d_in[2];
    const float* mask = (const float*)d_in[3];
    const float* Wq   = (const float*)d_in[4];
    const float* bq   = (const float*)d_in[5];
    const float* Wk   = (const float*)d_in[6];
    const float* bk   = (const float*)d_in[7];
    const float* Wv   = (const float*)d_in[8];
    const float* bv   = (const float*)d_in[9];
    const float* Wg   = (const float*)d_in[10];
    const float* bg   = (const float*)d_in[11];
    float* out = (float*)d_out;

    float *qp, *kp, *vp, *x, *S;
    cudaGetSymbolAddress((void**)&qp, g_qp);
    cudaGetSymbolAddress((void**)&kp, g_kp);
    cudaGetSymbolAddress((void**)&vp, g_vp);
    cudaGetSymbolAddress((void**)&x,  g_x);
    cudaGetSymbolAddress((void**)&S,  g_S);

    const dim3 blk(256);
    const long long LD = (long long)L_ * D_;
    const long long LL = (long long)L_ * L_;

    // 1) projections: qp/kp/vp = in @ W + b   [16384x1024] x [1024x1024]
    {
        dim3 g(D_ / 128, M_ / 128, 1);
        gemm_k<false, 0, false><<<g, blk>>>(q, nullptr, Wq, bq, qp,
            M_, D_, D_, 0, 0, 0, 1.0f, nullptr, nullptr, nullptr);
        gemm_k<false, 0, false><<<g, blk>>>(k, nullptr, Wk, bk, kp,
            M_, D_, D_, 0, 0, 0, 1.0f, nullptr, nullptr, nullptr);
        gemm_k<false, 0, false><<<g, blk>>>(v, nullptr, Wv, bv, vp,
            M_, D_, D_, 0, 0, 0, 1.0f, nullptr, nullptr, nullptr);
    }

    // 2) scores: S[b] = (qp[b] @ kp[b]^T) * (1/sqrt(D))   [2048x2048] per batch
    {
        dim3 g(L_ / 128, L_ / 128, B_);
        gemm_k<true, 1, false><<<g, blk>>>(qp, nullptr, kp, nullptr, S,
            L_, L_, D_, LD, LD, LL, 0.03125f, nullptr, nullptr, nullptr);
    }

    // 3) row softmax
    softmax_k<<<M_, 256>>>(S);

    // 4) x[b] = P[b] @ vp[b]   [2048x2048] x [2048x1024] per batch
    {
        dim3 g(D_ / 128, L_ / 128, B_);
        gemm_k<false, 0, false><<<g, blk>>>(S, nullptr, vp, nullptr, x,
            L_, D_, L_, LL, LD, LD, 1.0f, nullptr, nullptr, nullptr);
    }

    // 5) gate GEMM + fused epilogue -> d_out
    //    gate = [qp, x] @ Wg + bg ; out = x * mask * sigmoid(gate) + q
    {
        dim3 g(D_ / 128, M_ / 128, 1);
        gemm_k<false, 2, true><<<g, blk>>>(qp, x, Wg, bg, out,
            M_, D_, 2 * D_, 0, 0, 0, 1.0f, x, q, mask);
    }
}

// round 3
// speedup vs baseline: 1.7851x; 1.7851x over previous
#include <cuda_runtime.h>
#include <cuda_bf16.h>
#include <cstdint>
#include <math.h>

#define BB 8
#define LLEN 2048
#define DDIM 1024
#define MTOT (BB * LLEN)          // 16384

// ---------------------------------------------------------------------------
// Scratch (__device__ globals; allocation-free per harness rules)
// ---------------------------------------------------------------------------
__device__ __nv_bfloat16 g_qh[MTOT * DDIM], g_ql[MTOT * DDIM];
__device__ __nv_bfloat16 g_kh[MTOT * DDIM], g_kl[MTOT * DDIM];
__device__ __nv_bfloat16 g_vh[MTOT * DDIM], g_vl[MTOT * DDIM];
__device__ __nv_bfloat16 g_Wqth[DDIM * DDIM], g_Wqtl[DDIM * DDIM];
__device__ __nv_bfloat16 g_Wkth[DDIM * DDIM], g_Wktl[DDIM * DDIM];
__device__ __nv_bfloat16 g_Wvth[DDIM * DDIM], g_Wvtl[DDIM * DDIM];
__device__ __nv_bfloat16 g_Wgth[DDIM * 2 * DDIM], g_Wgtl[DDIM * 2 * DDIM];
__device__ __nv_bfloat16 g_qph[MTOT * DDIM], g_qpl[MTOT * DDIM];
__device__ __nv_bfloat16 g_kph[MTOT * DDIM], g_kpl[MTOT * DDIM];
__device__ __nv_bfloat16 g_vph[MTOT * DDIM], g_vpl[MTOT * DDIM];
__device__ __nv_bfloat16 g_vpTh[MTOT * DDIM], g_vpTl[MTOT * DDIM];
__device__ float         g_S[BB * LLEN * LLEN];          // 134 MB
__device__ __nv_bfloat16 g_Ph[BB * LLEN * LLEN], g_Pl[BB * LLEN * LLEN];
__device__ __nv_bfloat16 g_xh[MTOT * DDIM], g_xl[MTOT * DDIM];

// ---------------------------------------------------------------------------
// helpers
// ---------------------------------------------------------------------------
__device__ __forceinline__ uint32_t smem_u32(const void* p) {
    uint32_t a;
    asm("{ .reg .u64 t; cvta.to.shared.u64 t, %1; cvt.u32.u64 %0, t; }"
        : "=r"(a) : "l"(p));
    return a;
}
__device__ __forceinline__ void cp16(uint32_t d, const void* s) {
    asm volatile("cp.async.cg.shared.global [%0], [%1], 16;"
                 :: "r"(d), "l"(s) : "memory");
}
__device__ __forceinline__ void cp_commit() {
    asm volatile("cp.async.commit_group;" ::: "memory");
}
template <int N>
__device__ __forceinline__ void cp_wait() {
    asm volatile("cp.async.wait_group %0;" :: "n"(N) : "memory");
}
__device__ __forceinline__ void ldsm4(uint32_t addr, uint32_t* r) {
    asm volatile("ldmatrix.sync.aligned.m8n8.x4.shared.b16 {%0,%1,%2,%3}, [%4];"
                 : "=r"(r[0]), "=r"(r[1]), "=r"(r[2]), "=r"(r[3]) : "r"(addr));
}
__device__ __forceinline__ void mma16816(float* c, const uint32_t* a,
                                         uint32_t b0, uint32_t b1) {
    asm volatile(
        "mma.sync.aligned.m16n8k16.row.col.f32.bf16.bf16.f32 "
        "{%0,%1,%2,%3}, {%4,%5,%6,%7}, {%8,%9}, {%0,%1,%2,%3};"
        : "+f"(c[0]), "+f"(c[1]), "+f"(c[2]), "+f"(c[3])
        : "r"(a[0]), "r"(a[1]), "r"(a[2]), "r"(a[3]), "r"(b0), "r"(b1));
}

#define SWZ(o) ((o) ^ (((o) >> 3) & 0x70))

__device__ __forceinline__ uint32_t bfpack(__nv_bfloat16 a, __nv_bfloat16 b) {
    return (uint32_t)__bfloat16_as_ushort(a) | ((uint32_t)__bfloat16_as_ushort(b) << 16);
}
__device__ __forceinline__ float bfu_lo(uint32_t w) {
    return __bfloat162float(__ushort_as_bfloat16((unsigned short)(w & 0xFFFF)));
}
__device__ __forceinline__ float bfu_hi(uint32_t w) {
    return __bfloat162float(__ushort_as_bfloat16((unsigned short)(w >> 16)));
}

// ---------------------------------------------------------------------------
// HMMA GEMM: C[M,N] = epi( (Ahi+Alo)[M,K] @ (Bhi+Blo)[N,K]^T )
//   CTA tile 128x128, BK=64, 3-stage cp.async pipeline, 8 warps (32x64 each)
//   hi/lo split: acc += Ah*Bh + Ah*Bl + Al*Bh
//   EPI 0: +bias (nullable), write bf16 hi/lo
//   EPI 1: *alpha, write fp32
//   EPI 2: gate: out = (xhi+xlo)*mask*sigmoid(acc+bias) + q0, write fp32
// ---------------------------------------------------------------------------
template <int EPI, bool CONCAT>
__global__ __launch_bounds__(256, 1)
void mma_gemm(const __nv_bfloat16* __restrict__ Ahi, const __nv_bfloat16* __restrict__ Alo,
              const __nv_bfloat16* __restrict__ A2hi, const __nv_bfloat16* __restrict__ A2lo,
              int lda, int KA,
              const __nv_bfloat16* __restrict__ Bhi, const __nv_bfloat16* __restrict__ Blo,
              int ldb,
              const float* __restrict__ bias,
              float* __restrict__ Cf,
              __nv_bfloat16* __restrict__ Chi, __nv_bfloat16* __restrict__ Clo,
              int ldc, int K,
              long long sA, long long sB, long long sC, float alpha,
              const __nv_bfloat16* __restrict__ xhi, const __nv_bfloat16* __restrict__ xlo,
              const float* __restrict__ q0, const float* __restrict__ mask)
{
    extern __shared__ char dsm[];
    const uint32_t raw = smem_u32(dsm);
    const uint32_t abase = (raw + 1023u) & ~1023u;

    constexpr int TILE = 16384;                 // one 128x64 bf16 tile (swizzled)
    constexpr int OFF_AH = 0;                   // 3 stages each
    constexpr int OFF_AL = 3 * TILE;
    constexpr int OFF_BH = 6 * TILE;
    constexpr int OFF_BL = 9 * TILE;

    const int tid = threadIdx.x, wid = tid >> 5, lid = tid & 31;
    const int bn = blockIdx.x, bm = blockIdx.y, bz = blockIdx.z;

    Ahi += (long long)bz * sA;  Alo += (long long)bz * sA;
    Bhi += (long long)bz * sB;  Blo += (long long)bz * sB;
    if (EPI == 1 || EPI == 2) Cf += (long long)bz * sC;
    if (EPI == 0) { Chi += (long long)bz * sC; Clo += (long long)bz * sC; }

    const int rowA0 = bm * 128, rowB0 = bn * 128;

    auto stage = [&](int kt, int buf) {
        const int r = tid >> 3, seg = tid & 7;
        long long kc = (long long)kt * 64 + seg * 8;
        const __nv_bfloat16* pAh = Ahi;
        const __nv_bfloat16* pAl = Alo;
        long long kA = kc;
        if (CONCAT && kc >= KA) { pAh = A2hi; pAl = A2lo; kA = kc - KA; }
        #pragma unroll
        for (int i = 0; i < 4; ++i) {
            const int rr = i * 32 + r;
            const uint32_t so = SWZ(rr * 128 + seg * 16);
            cp16(abase + OFF_AH + buf * TILE + so, pAh + (long long)(rowA0 + rr) * lda + kA);
            cp16(abase + OFF_AL + buf * TILE + so, pAl + (long long)(rowA0 + rr) * lda + kA);
            cp16(abase + OFF_BH + buf * TILE + so, Bhi + (long long)(rowB0 + rr) * ldb + kc);
            cp16(abase + OFF_BL + buf * TILE + so, Blo + (long long)(rowB0 + rr) * ldb + kc);
        }
    };

    const int wm0 = (wid & 3) * 32;     // warp m offset (4 warps over 128)
    const int wn0 = (wid >> 2) * 64;    // warp n offset (2 warps over 128)
    const int r16 = lid & 15, hseg = lid >> 4;

    float acc[2][8][4] = {};

    const int nt = K / 64;
    stage(0, 0); cp_commit();
    stage(1, 1); cp_commit();

    for (int t = 0; t < nt; ++t) {
        if (t + 1 < nt) cp_wait<1>(); else cp_wait<0>();
        __syncthreads();
        if (t + 2 < nt) { stage(t + 2, (t + 2) % 3); cp_commit(); }

        const int buf = t % 3;
        const uint32_t ba_h = abase + OFF_AH + buf * TILE;
        const uint32_t ba_l = abase + OFF_AL + buf * TILE;
        const uint32_t bb_h = abase + OFF_BH + buf * TILE;
        const uint32_t bb_l = abase + OFF_BL + buf * TILE;

        #pragma unroll
        for (int s = 0; s < 4; ++s) {
            uint32_t ah[2][4], al[2][4], bh[4][4], bl[4][4];
            #pragma unroll
            for (int mf = 0; mf < 2; ++mf) {
                const uint32_t o = (uint32_t)((wm0 + mf * 16 + r16) * 128 + s * 32 + hseg * 16);
                ldsm4(ba_h + SWZ(o), ah[mf]);
                ldsm4(ba_l + SWZ(o), al[mf]);
            }
            #pragma unroll
            for (int g = 0; g < 4; ++g) {
                const uint32_t o = (uint32_t)((wn0 + g * 16 + r16) * 128 + s * 32 + hseg * 16);
                ldsm4(bb_h + SWZ(o), bh[g]);
                ldsm4(bb_l + SWZ(o), bl[g]);
            }
            #pragma unroll
            for (int mf = 0; mf < 2; ++mf) {
                #pragma unroll
                for (int nf = 0; nf < 8; ++nf) {
                    const int g = nf >> 1, o = nf & 1;
                    mma16816(acc[mf][nf], ah[mf], bh[g][o], bh[g][o + 2]);
                    mma16816(acc[mf][nf], ah[mf], bl[g][o], bl[g][o + 2]);
                    mma16816(acc[mf][nf], al[mf], bh[g][o], bh[g][o + 2]);
                }
            }
        }
        __syncthreads();
    }

    // ------------------- epilogue -------------------
    #pragma unroll
    for (int mf = 0; mf < 2; ++mf) {
        #pragma unroll
        for (int nf = 0; nf < 8; ++nf) {
            const int col = bn * 128 + wn0 + nf * 8 + (lid & 3) * 2;
            #pragma unroll
            for (int h = 0; h < 2; ++h) {
                const int row = bm * 128 + wm0 + mf * 16 + (lid >> 2) + h * 8;
                const long long off = (long long)row * ldc + col;
                float v0 = acc[mf][nf][h * 2 + 0];
                float v1 = acc[mf][nf][h * 2 + 1];

                if (EPI == 0) {
                    if (bias) {
                        const float2 b2 = *(const float2*)(bias + col);
                        v0 += b2.x; v1 += b2.y;
                    }
                    __nv_bfloat16 h0 = __float2bfloat16(v0), h1 = __float2bfloat16(v1);
                    __nv_bfloat16 l0 = __float2bfloat16(v0 - __bfloat162float(h0));
                    __nv_bfloat16 l1 = __float2bfloat16(v1 - __bfloat162float(h1));
                    *(uint32_t*)(Chi + off) = bfpack(h0, h1);
                    *(uint32_t*)(Clo + off) = bfpack(l0, l1);
                } else if (EPI == 1) {
                    *(float2*)(Cf + off) = make_float2(v0 * alpha, v1 * alpha);
                } else {
                    const float mv = mask[row];
                    const float2 b2 = *(const float2*)(bias + col);
                    const uint32_t xh2 = *(const uint32_t*)(xhi + off);
                    const uint32_t xl2 = *(const uint32_t*)(xlo + off);
                    const float2 q2 = *(const float2*)(q0 + off);
                    const float g0 = v0 + b2.x, g1 = v1 + b2.y;
                    const float s0 = 1.0f / (1.0f + __expf(-g0));
                    const float s1 = 1.0f / (1.0f + __expf(-g1));
                    const float x0 = bfu_lo(xh2) + bfu_lo(xl2);
                    const float x1 = bfu_hi(xh2) + bfu_hi(xl2);
                    *(float2*)(Cf + off) = make_float2(x0 * mv * s0 + q2.x,
                                                       x1 * mv * s1 + q2.y);
                }
            }
        }
    }
}

// ---------------------------------------------------------------------------
// fp32 -> bf16 hi/lo split (elementwise)
// ---------------------------------------------------------------------------
__global__ __launch_bounds__(256)
void split_k(const float* __restrict__ X, __nv_bfloat16* __restrict__ H,
             __nv_bfloat16* __restrict__ L)
{
    const long long i = ((long long)blockIdx.x * 256 + threadIdx.x) * 4;
    float4 v = *(const float4*)(X + i);
    float vv[4] = {v.x, v.y, v.z, v.w};
    uint32_t hw[2], lw[2];
    #pragma unroll
    for (int p = 0; p < 2; ++p) {
        __nv_bfloat16 h0 = __float2bfloat16(vv[2 * p]);
        __nv_bfloat16 h1 = __float2bfloat16(vv[2 * p + 1]);
        __nv_bfloat16 l0 = __float2bfloat16(vv[2 * p] - __bfloat162float(h0));
        __nv_bfloat16 l1 = __float2bfloat16(vv[2 * p + 1] - __bfloat162float(h1));
        hw[p] = bfpack(h0, h1);
        lw[p] = bfpack(l0, l1);
    }
    *(uint2*)(H + i) = make_uint2(hw[0], hw[1]);
    *(uint2*)(L + i) = make_uint2(lw[0], lw[1]);
}

// W[R,C] fp32 -> T[C,R] bf16 hi/lo (transpose + split)
__global__ __launch_bounds__(256)
void transpose_split_k(const float* __restrict__ W, __nv_bfloat16* __restrict__ Th,
                       __nv_bfloat16* __restrict__ Tl, int R, int C)
{
    __shared__ float tile[32][33];
    const int tx = threadIdx.x, ty = threadIdx.y;
    const int x = blockIdx.x * 32 + tx;
    const int y0 = blockIdx.y * 32;
    #pragma unroll
    for (int j = ty; j < 32; j += 8)
        tile[j][tx] = W[(long long)(y0 + j) * C + x];
    __syncthreads();
    const int ox = y0 + tx;
    const int oy0 = blockIdx.x * 32;
    #pragma unroll
    for (int j = ty; j < 32; j += 8) {
        const float v = tile[tx][j];
        __nv_bfloat16 h = __float2bfloat16(v);
        Th[(long long)(oy0 + j) * R + ox] = h;
        Tl[(long long)(oy0 + j) * R + ox] = __float2bfloat16(v - __bfloat162float(h));
    }
}

// bf16 transpose: X[R,C] -> T[C,R]
__global__ __launch_bounds__(256)
void transpose_bf16_k(const __nv_bfloat16* __restrict__ X, __nv_bfloat16* __restrict__ T,
                      int R, int C)
{
    __shared__ __nv_bfloat16 tile[32][34];
    const int tx = threadIdx.x, ty = threadIdx.y;
    const int x = blockIdx.x * 32 + tx;
    const int y0 = blockIdx.y * 32;
    #pragma unroll
    for (int j = ty; j < 32; j += 8)
        tile[j][tx] = X[(long long)(y0 + j) * C + x];
    __syncthreads();
    const int ox = y0 + tx;
    const int oy0 = blockIdx.x * 32;
    #pragma unroll
    for (int j = ty; j < 32; j += 8)
        T[(long long)(oy0 + j) * R + ox] = tile[tx][j];
}

// Row softmax over S (rows of 2048 fp32) -> P hi/lo bf16
__global__ __launch_bounds__(256)
void softmax_split_k(const float* __restrict__ S, __nv_bfloat16* __restrict__ Ph,
                     __nv_bfloat16* __restrict__ Pl)
{
    const long long base = (long long)blockIdx.x * LLEN;
    const float* row = S + base;
    const int tid = threadIdx.x;

    float v[8];
    #pragma unroll
    for (int i = 0; i < 8; ++i) v[i] = row[tid + 256 * i];

    float mx = v[0];
    #pragma unroll
    for (int i = 1; i < 8; ++i) mx = fmaxf(mx, v[i]);
    #pragma unroll
    for (int o = 16; o > 0; o >>= 1)
        mx = fmaxf(mx, __shfl_xor_sync(0xffffffffu, mx, o));

    __shared__ float red[8];
    if ((tid & 31) == 0) red[tid >> 5] = mx;
    __syncthreads();
    mx = red[0];
    #pragma unroll
    for (int i = 1; i < 8; ++i) mx = fmaxf(mx, red[i]);
    __syncthreads();

    float s = 0.0f;
    #pragma unroll
    for (int i = 0; i < 8; ++i) { v[i] = __expf(v[i] - mx); s += v[i]; }
    #pragma unroll
    for (int o = 16; o > 0; o >>= 1)
        s += __shfl_xor_sync(0xffffffffu, s, o);
    if ((tid & 31) == 0) red[tid >> 5] = s;
    __syncthreads();
    s = 0.0f;
    #pragma unroll
    for (int i = 0; i < 8; ++i) s += red[i];

    const float inv = 1.0f / s;
    #pragma unroll
    for (int i = 0; i < 8; ++i) {
        const float p = v[i] * inv;
        const long long idx = base + tid + 256 * i;
        __nv_bfloat16 h = __float2bfloat16(p);
        Ph[idx] = h;
        Pl[idx] = __float2bfloat16(p - __bfloat162float(h));
    }
}

// ---------------------------------------------------------------------------
// Host
// ---------------------------------------------------------------------------
extern "C" void kernel_launch(void* const* d_in, const int* in_sizes, int n_in,
                              void* d_out, int out_size)
{
    const float* q    = (const float*)d_in[0];
    const float* k    = (const float*)d_in[1];
    const float* v    = (const float*)d_in[2];
    const float* mask = (const float*)d_in[3];
    const float* Wq   = (const float*)d_in[4];
    const float* bq   = (const float*)d_in[5];
    const float* Wk   = (const float*)d_in[6];
    const float* bk   = (const float*)d_in[7];
    const float* Wv   = (const float*)d_in[8];
    const float* bv   = (const float*)d_in[9];
    const float* Wg   = (const float*)d_in[10];
    const float* bg   = (const float*)d_in[11];
    float* out = (float*)d_out;

    #define SYM(p, s) void* p##_; cudaGetSymbolAddress(&p##_, s); \
                      __nv_bfloat16* p = (__nv_bfloat16*)p##_;
    SYM(qh, g_qh)   SYM(ql, g_ql)   SYM(kh, g_kh)   SYM(kl, g_kl)
    SYM(vh, g_vh)   SYM(vl, g_vl)
    SYM(Wqth, g_Wqth) SYM(Wqtl, g_Wqtl) SYM(Wkth, g_Wkth) SYM(Wktl, g_Wktl)
    SYM(Wvth, g_Wvth) SYM(Wvtl, g_Wvtl) SYM(Wgth, g_Wgth) SYM(Wgtl, g_Wgtl)
    SYM(qph, g_qph) SYM(qpl, g_qpl) SYM(kph, g_kph) SYM(kpl, g_kpl)
    SYM(vph, g_vph) SYM(vpl, g_vpl) SYM(vpTh, g_vpTh) SYM(vpTl, g_vpTl)
    SYM(Ph, g_Ph)   SYM(Pl, g_Pl)   SYM(xh, g_xh)   SYM(xl, g_xl)
    #undef SYM
    void* S_; cudaGetSymbolAddress(&S_, g_S); float* S = (float*)S_;

    const int SMEM_DYN = 12 * 16384 + 1024;   // 3-stage x 4 tiles + align pad
    cudaFuncSetAttribute(mma_gemm<0, false>, cudaFuncAttributeMaxDynamicSharedMemorySize, SMEM_DYN);
    cudaFuncSetAttribute(mma_gemm<1, false>, cudaFuncAttributeMaxDynamicSharedMemorySize, SMEM_DYN);
    cudaFuncSetAttribute(mma_gemm<2, true>,  cudaFuncAttributeMaxDynamicSharedMemorySize, SMEM_DYN);

    const long long LD = (long long)LLEN * DDIM;   // 2M
    const long long LLsq = (long long)LLEN * LLEN; // 4M

    // 1) split inputs to bf16 hi/lo
    split_k<<<MTOT * DDIM / 1024, 256>>>(q, qh, ql);
    split_k<<<MTOT * DDIM / 1024, 256>>>(k, kh, kl);
    split_k<<<MTOT * DDIM / 1024, 256>>>(v, vh, vl);

    // 2) transpose + split weights: W[K,N] -> Wt[N,K]
    {
        dim3 b(32, 8);
        transpose_split_k<<<dim3(32, 32), b>>>(Wq, Wqth, Wqtl, DDIM, DDIM);
        transpose_split_k<<<dim3(32, 32), b>>>(Wk, Wkth, Wktl, DDIM, DDIM);
        transpose_split_k<<<dim3(32, 32), b>>>(Wv, Wvth, Wvtl, DDIM, DDIM);
        transpose_split_k<<<dim3(32, 64), b>>>(Wg, Wgth, Wgtl, 2 * DDIM, DDIM);
    }

    // 3) projections: qp/kp/vp = in @ W + b  (M=16384, N=1024, K=1024)
    {
        dim3 g(DDIM / 128, MTOT / 128, 1);
        mma_gemm<0, false><<<g, 256, SMEM_DYN>>>(qh, ql, nullptr, nullptr, DDIM, 0,
            Wqth, Wqtl, DDIM, bq, nullptr, qph, qpl, DDIM, DDIM, 0, 0, 0, 0.f,
            nullptr, nullptr, nullptr, nullptr);
        mma_gemm<0, false><<<g, 256, SMEM_DYN>>>(kh, kl, nullptr, nullptr, DDIM, 0,
            Wkth, Wktl, DDIM, bk, nullptr, kph, kpl, DDIM, DDIM, 0, 0, 0, 0.f,
            nullptr, nullptr, nullptr, nullptr);
        mma_gemm<0, false><<<g, 256, SMEM_DYN>>>(vh, vl, nullptr, nullptr, DDIM, 0,
            Wvth, Wvtl, DDIM, bv, nullptr, vph, vpl, DDIM, DDIM, 0, 0, 0, 0.f,
            nullptr, nullptr, nullptr, nullptr);
    }

    // 4) transpose vp -> vpT [D, M]
    {
        dim3 b(32, 8);
        transpose_bf16_k<<<dim3(32, 512), b>>>(vph, vpTh, MTOT, DDIM);
        transpose_bf16_k<<<dim3(32, 512), b>>>(vpl, vpTl, MTOT, DDIM);
    }

    // 5) scores: S[b] = (qp[b] @ kp[b]^T) / 32  (per batch 2048x2048, K=1024)
    {
        dim3 g(LLEN / 128, LLEN / 128, BB);
        mma_gemm<1, false><<<g, 256, SMEM_DYN>>>(qph, qpl, nullptr, nullptr, DDIM, 0,
            kph, kpl, DDIM, nullptr, S, nullptr, nullptr, LLEN, DDIM,
            LD, LD, LLsq, 0.03125f, nullptr, nullptr, nullptr, nullptr);
    }

    // 6) softmax -> P hi/lo
    softmax_split_k<<<MTOT, 256>>>(S, Ph, Pl);

    // 7) x[b] = P[b] @ vp[b]  (B operand = vpT slice, ldb = MTOT)
    {
        dim3 g(DDIM / 128, LLEN / 128, BB);
        mma_gemm<0, false><<<g, 256, SMEM_DYN>>>(Ph, Pl, nullptr, nullptr, LLEN, 0,
            vpTh, vpTl, MTOT, nullptr, nullptr, xh, xl, DDIM, LLEN,
            LLsq, LLEN, LD, 0.f, nullptr, nullptr, nullptr, nullptr);
    }

    // 8) gate GEMM + fused epilogue -> d_out
    {
        dim3 g(DDIM / 128, MTOT / 128, 1);
        mma_gemm<2, true><<<g, 256, SMEM_DYN>>>(qph, qpl, xh, xl, DDIM, DDIM,
            Wgth, Wgtl, 2 * DDIM, bg, out, nullptr, nullptr, DDIM, 2 * DDIM,
            0, 0, 0, 0.f, xh, xl, q, mask);
    }
}

// round 5
// speedup vs baseline: 2.7962x; 1.5664x over previous
#include <cuda_runtime.h>
#include <cuda_bf16.h>
#include <cstdint>
#include <math.h>

#define BB 8
#define LLEN 2048
#define DDIM 1024
#define MTOT (BB * LLEN)          // 16384

// ---------------------------------------------------------------------------
// Scratch (__device__ globals; allocation-free per harness rules)
// ---------------------------------------------------------------------------
__device__ __nv_bfloat16 g_qh[MTOT * DDIM], g_ql[MTOT * DDIM];
__device__ __nv_bfloat16 g_kh[MTOT * DDIM], g_kl[MTOT * DDIM];
__device__ __nv_bfloat16 g_vh[MTOT * DDIM], g_vl[MTOT * DDIM];
__device__ __nv_bfloat16 g_Wqth[DDIM * DDIM], g_Wqtl[DDIM * DDIM];
__device__ __nv_bfloat16 g_Wkth[DDIM * DDIM], g_Wktl[DDIM * DDIM];
__device__ __nv_bfloat16 g_Wvth[DDIM * DDIM], g_Wvtl[DDIM * DDIM];
__device__ __nv_bfloat16 g_Wgth[DDIM * 2 * DDIM], g_Wgtl[DDIM * 2 * DDIM];
__device__ __nv_bfloat16 g_qph[MTOT * DDIM], g_qpl[MTOT * DDIM];
__device__ __nv_bfloat16 g_kph[MTOT * DDIM], g_kpl[MTOT * DDIM];
__device__ __nv_bfloat16 g_vph[MTOT * DDIM], g_vpl[MTOT * DDIM];
__device__ __nv_bfloat16 g_vpTh[MTOT * DDIM], g_vpTl[MTOT * DDIM];
__device__ float         g_S[BB * LLEN * LLEN];          // 134 MB
__device__ __nv_bfloat16 g_Ph[BB * LLEN * LLEN], g_Pl[BB * LLEN * LLEN];
__device__ __nv_bfloat16 g_xh[MTOT * DDIM], g_xl[MTOT * DDIM];

// ---------------------------------------------------------------------------
// helpers
// ---------------------------------------------------------------------------
__device__ __forceinline__ uint32_t smem_u32(const void* p) {
    uint32_t a;
    asm("{ .reg .u64 t; cvta.to.shared.u64 t, %1; cvt.u32.u64 %0, t; }"
        : "=r"(a) : "l"(p));
    return a;
}
__device__ __forceinline__ void cp16(uint32_t d, const void* s) {
    asm volatile("cp.async.cg.shared.global [%0], [%1], 16;"
                 :: "r"(d), "l"(s) : "memory");
}
__device__ __forceinline__ void cp_commit() {
    asm volatile("cp.async.commit_group;" ::: "memory");
}
template <int N>
__device__ __forceinline__ void cp_wait() {
    asm volatile("cp.async.wait_group %0;" :: "n"(N) : "memory");
}
__device__ __forceinline__ void ldsm4(uint32_t addr, uint32_t* r) {
    asm volatile("ldmatrix.sync.aligned.m8n8.x4.shared.b16 {%0,%1,%2,%3}, [%4];"
                 : "=r"(r[0]), "=r"(r[1]), "=r"(r[2]), "=r"(r[3]) : "r"(addr));
}
__device__ __forceinline__ void mma16816(float* c, const uint32_t* a,
                                         uint32_t b0, uint32_t b1) {
    asm volatile(
        "mma.sync.aligned.m16n8k16.row.col.f32.bf16.bf16.f32 "
        "{%0,%1,%2,%3}, {%4,%5,%6,%7}, {%8,%9}, {%0,%1,%2,%3};"
        : "+f"(c[0]), "+f"(c[1]), "+f"(c[2]), "+f"(c[3])
        : "r"(a[0]), "r"(a[1]), "r"(a[2]), "r"(a[3]), "r"(b0), "r"(b1));
}

#define SWZ(o) ((o) ^ (((o) >> 3) & 0x70))

__device__ __forceinline__ uint32_t bfpack(__nv_bfloat16 a, __nv_bfloat16 b) {
    return (uint32_t)__bfloat16_as_ushort(a) | ((uint32_t)__bfloat16_as_ushort(b) << 16);
}
__device__ __forceinline__ float bfu_lo(uint32_t w) {
    return __bfloat162float(__ushort_as_bfloat16((unsigned short)(w & 0xFFFF)));
}
__device__ __forceinline__ float bfu_hi(uint32_t w) {
    return __bfloat162float(__ushort_as_bfloat16((unsigned short)(w >> 16)));
}

// ---------------------------------------------------------------------------
// HMMA GEMM: C[M,N] = epi( (Ahi+Alo)[M,K] @ (Bhi+Blo)[N,K]^T )
//   CTA tile 128x128, BK=64, 3-stage cp.async pipeline, 8 warps (32x64 each)
//   hi/lo split: acc += Ah*Bh + Ah*Bl + Al*Bh  (pass-major for ILP)
//   EPI 0: +bias (nullable), write bf16 hi/lo
//   EPI 1: *alpha, write fp32
//   EPI 2: gate: out = (xhi+xlo)*mask*sigmoid(acc+bias) + q0, write fp32
// ---------------------------------------------------------------------------
template <int EPI, bool CONCAT>
__global__ __launch_bounds__(256, 1)
void mma_gemm(const __nv_bfloat16* __restrict__ Ahi, const __nv_bfloat16* __restrict__ Alo,
              const __nv_bfloat16* __restrict__ A2hi, const __nv_bfloat16* __restrict__ A2lo,
              int lda, int KA,
              const __nv_bfloat16* __restrict__ Bhi, const __nv_bfloat16* __restrict__ Blo,
              int ldb,
              const float* __restrict__ bias,
              float* __restrict__ Cf,
              __nv_bfloat16* __restrict__ Chi, __nv_bfloat16* __restrict__ Clo,
              int ldc, int K,
              long long sA, long long sB, long long sC, float alpha,
              const __nv_bfloat16* __restrict__ xhi, const __nv_bfloat16* __restrict__ xlo,
              const float* __restrict__ q0, const float* __restrict__ mask)
{
    extern __shared__ char dsm[];
    const uint32_t raw = smem_u32(dsm);
    const uint32_t abase = (raw + 1023u) & ~1023u;

    constexpr int TILE = 16384;                 // one 128x64 bf16 tile (swizzled)
    constexpr int OFF_AH = 0;                   // 3 stages each
    constexpr int OFF_AL = 3 * TILE;
    constexpr int OFF_BH = 6 * TILE;
    constexpr int OFF_BL = 9 * TILE;

    const int tid = threadIdx.x, wid = tid >> 5, lid = tid & 31;
    const int bn = blockIdx.x, bm = blockIdx.y, bz = blockIdx.z;

    Ahi += (long long)bz * sA;  Alo += (long long)bz * sA;
    Bhi += (long long)bz * sB;  Blo += (long long)bz * sB;
    if (EPI == 1 || EPI == 2) Cf += (long long)bz * sC;
    if (EPI == 0) { Chi += (long long)bz * sC; Clo += (long long)bz * sC; }

    const int rowA0 = bm * 128, rowB0 = bn * 128;

    auto stage = [&](int kt, int buf) {
        const int r = tid >> 3, seg = tid & 7;
        long long kc = (long long)kt * 64 + seg * 8;
        const __nv_bfloat16* pAh = Ahi;
        const __nv_bfloat16* pAl = Alo;
        long long kA = kc;
        if (CONCAT && kc >= KA) { pAh = A2hi; pAl = A2lo; kA = kc - KA; }
        #pragma unroll
        for (int i = 0; i < 4; ++i) {
            const int rr = i * 32 + r;
            const uint32_t so = SWZ(rr * 128 + seg * 16);
            cp16(abase + OFF_AH + buf * TILE + so, pAh + (long long)(rowA0 + rr) * lda + kA);
            cp16(abase + OFF_AL + buf * TILE + so, pAl + (long long)(rowA0 + rr) * lda + kA);
            cp16(abase + OFF_BH + buf * TILE + so, Bhi + (long long)(rowB0 + rr) * ldb + kc);
            cp16(abase + OFF_BL + buf * TILE + so, Blo + (long long)(rowB0 + rr) * ldb + kc);
        }
    };

    const int wm0 = (wid & 3) * 32;     // warp m offset (4 warps over 128)
    const int wn0 = (wid >> 2) * 64;    // warp n offset (2 warps over 128)
    const int r16 = lid & 15, hseg = lid >> 4;

    float acc[2][8][4] = {};

    const int nt = K / 64;
    stage(0, 0); cp_commit();
    stage(1, 1); cp_commit();

    for (int t = 0; t < nt; ++t) {
        if (t + 1 < nt) cp_wait<1>(); else cp_wait<0>();
        __syncthreads();
        // staging buffer (t+2)%3 is not read this iteration, and every thread
        // has finished reading it (as buffer t-1) before the barrier above.
        if (t + 2 < nt) { stage(t + 2, (t + 2) % 3); cp_commit(); }

        const int buf = t % 3;
        const uint32_t ba_h = abase + OFF_AH + buf * TILE;
        const uint32_t ba_l = abase + OFF_AL + buf * TILE;
        const uint32_t bb_h = abase + OFF_BH + buf * TILE;
        const uint32_t bb_l = abase + OFF_BL + buf * TILE;

        #pragma unroll
        for (int s = 0; s < 4; ++s) {
            uint32_t ah[2][4], al[2][4], bh[4][4], bl[4][4];
            #pragma unroll
            for (int mf = 0; mf < 2; ++mf) {
                const uint32_t o = (uint32_t)((wm0 + mf * 16 + r16) * 128 + s * 32 + hseg * 16);
                ldsm4(ba_h + SWZ(o), ah[mf]);
                ldsm4(ba_l + SWZ(o), al[mf]);
            }
            #pragma unroll
            for (int g = 0; g < 4; ++g) {
                const uint32_t o = (uint32_t)((wn0 + g * 16 + r16) * 128 + s * 32 + hseg * 16);
                ldsm4(bb_h + SWZ(o), bh[g]);
                ldsm4(bb_l + SWZ(o), bl[g]);
            }
            // pass-major: 16 independent MMAs per pass -> dependency distance 16
            #pragma unroll
            for (int mf = 0; mf < 2; ++mf)
                #pragma unroll
                for (int nf = 0; nf < 8; ++nf) {
                    const int g = nf >> 1, o = nf & 1;
                    mma16816(acc[mf][nf], ah[mf], bh[g][o], bh[g][o + 2]);
                }
            #pragma unroll
            for (int mf = 0; mf < 2; ++mf)
                #pragma unroll
                for (int nf = 0; nf < 8; ++nf) {
                    const int g = nf >> 1, o = nf & 1;
                    mma16816(acc[mf][nf], ah[mf], bl[g][o], bl[g][o + 2]);
                }
            #pragma unroll
            for (int mf = 0; mf < 2; ++mf)
                #pragma unroll
                for (int nf = 0; nf < 8; ++nf) {
                    const int g = nf >> 1, o = nf & 1;
                    mma16816(acc[mf][nf], al[mf], bh[g][o], bh[g][o + 2]);
                }
        }
        // no trailing barrier: next iteration's cp_wait + barrier provide
        // the ordering before any buffer is overwritten.
    }

    // ------------------- epilogue -------------------
    #pragma unroll
    for (int mf = 0; mf < 2; ++mf) {
        #pragma unroll
        for (int nf = 0; nf < 8; ++nf) {
            const int col = bn * 128 + wn0 + nf * 8 + (lid & 3) * 2;
            #pragma unroll
            for (int h = 0; h < 2; ++h) {
                const int row = bm * 128 + wm0 + mf * 16 + (lid >> 2) + h * 8;
                const long long off = (long long)row * ldc + col;
                float v0 = acc[mf][nf][h * 2 + 0];
                float v1 = acc[mf][nf][h * 2 + 1];

                if (EPI == 0) {
                    if (bias) {
                        const float2 b2 = *(const float2*)(bias + col);
                        v0 += b2.x; v1 += b2.y;
                    }
                    __nv_bfloat16 h0 = __float2bfloat16(v0), h1 = __float2bfloat16(v1);
                    __nv_bfloat16 l0 = __float2bfloat16(v0 - __bfloat162float(h0));
                    __nv_bfloat16 l1 = __float2bfloat16(v1 - __bfloat162float(h1));
                    *(uint32_t*)(Chi + off) = bfpack(h0, h1);
                    *(uint32_t*)(Clo + off) = bfpack(l0, l1);
                } else if (EPI == 1) {
                    *(float2*)(Cf + off) = make_float2(v0 * alpha, v1 * alpha);
                } else {
                    const float mv = mask[row];
                    const float2 b2 = *(const float2*)(bias + col);
                    const uint32_t xh2 = *(const uint32_t*)(xhi + off);
                    const uint32_t xl2 = *(const uint32_t*)(xlo + off);
                    const float2 q2 = *(const float2*)(q0 + off);
                    const float g0 = v0 + b2.x, g1 = v1 + b2.y;
                    const float s0 = 1.0f / (1.0f + __expf(-g0));
                    const float s1 = 1.0f / (1.0f + __expf(-g1));
                    const float x0 = bfu_lo(xh2) + bfu_lo(xl2);
                    const float x1 = bfu_hi(xh2) + bfu_hi(xl2);
                    *(float2*)(Cf + off) = make_float2(x0 * mv * s0 + q2.x,
                                                       x1 * mv * s1 + q2.y);
                }
            }
        }
    }
}

// ---------------------------------------------------------------------------
// fp32 -> bf16 hi/lo split (elementwise)
// ---------------------------------------------------------------------------
__global__ __launch_bounds__(256)
void split_k(const float* __restrict__ X, __nv_bfloat16* __restrict__ H,
             __nv_bfloat16* __restrict__ L)
{
    const long long i = ((long long)blockIdx.x * 256 + threadIdx.x) * 4;
    float4 v = *(const float4*)(X + i);
    float vv[4] = {v.x, v.y, v.z, v.w};
    uint32_t hw[2], lw[2];
    #pragma unroll
    for (int p = 0; p < 2; ++p) {
        __nv_bfloat16 h0 = __float2bfloat16(vv[2 * p]);
        __nv_bfloat16 h1 = __float2bfloat16(vv[2 * p + 1]);
        __nv_bfloat16 l0 = __float2bfloat16(vv[2 * p] - __bfloat162float(h0));
        __nv_bfloat16 l1 = __float2bfloat16(vv[2 * p + 1] - __bfloat162float(h1));
        hw[p] = bfpack(h0, h1);
        lw[p] = bfpack(l0, l1);
    }
    *(uint2*)(H + i) = make_uint2(hw[0], hw[1]);
    *(uint2*)(L + i) = make_uint2(lw[0], lw[1]);
}

// W[R,C] fp32 -> T[C,R] bf16 hi/lo (transpose + split)
__global__ __launch_bounds__(256)
void transpose_split_k(const float* __restrict__ W, __nv_bfloat16* __restrict__ Th,
                       __nv_bfloat16* __restrict__ Tl, int R, int C)
{
    __shared__ float tile[32][33];
    const int tx = threadIdx.x, ty = threadIdx.y;
    const int x = blockIdx.x * 32 + tx;
    const int y0 = blockIdx.y * 32;
    #pragma unroll
    for (int j = ty; j < 32; j += 8)
        tile[j][tx] = W[(long long)(y0 + j) * C + x];
    __syncthreads();
    const int ox = y0 + tx;
    const int oy0 = blockIdx.x * 32;
    #pragma unroll
    for (int j = ty; j < 32; j += 8) {
        const float v = tile[tx][j];
        __nv_bfloat16 h = __float2bfloat16(v);
        Th[(long long)(oy0 + j) * R + ox] = h;
        Tl[(long long)(oy0 + j) * R + ox] = __float2bfloat16(v - __bfloat162float(h));
    }
}

// bf16 transpose: X[R,C] -> T[C,R]
__global__ __launch_bounds__(256)
void transpose_bf16_k(const __nv_bfloat16* __restrict__ X, __nv_bfloat16* __restrict__ T,
                      int R, int C)
{
    __shared__ __nv_bfloat16 tile[32][34];
    const int tx = threadIdx.x, ty = threadIdx.y;
    const int x = blockIdx.x * 32 + tx;
    const int y0 = blockIdx.y * 32;
    #pragma unroll
    for (int j = ty; j < 32; j += 8)
        tile[j][tx] = X[(long long)(y0 + j) * C + x];
    __syncthreads();
    const int ox = y0 + tx;
    const int oy0 = blockIdx.x * 32;
    #pragma unroll
    for (int j = ty; j < 32; j += 8)
        T[(long long)(oy0 + j) * R + ox] = tile[tx][j];
}

// Row softmax over S (rows of 2048 fp32) -> P hi/lo bf16
__global__ __launch_bounds__(256)
void softmax_split_k(const float* __restrict__ S, __nv_bfloat16* __restrict__ Ph,
                     __nv_bfloat16* __restrict__ Pl)
{
    const long long base = (long long)blockIdx.x * LLEN;
    const float* row = S + base;
    const int tid = threadIdx.x;

    float v[8];
    #pragma unroll
    for (int i = 0; i < 8; ++i) v[i] = row[tid + 256 * i];

    float mx = v[0];
    #pragma unroll
    for (int i = 1; i < 8; ++i) mx = fmaxf(mx, v[i]);
    #pragma unroll
    for (int o = 16; o > 0; o >>= 1)
        mx = fmaxf(mx, __shfl_xor_sync(0xffffffffu, mx, o));

    __shared__ float red[8];
    if ((tid & 31) == 0) red[tid >> 5] = mx;
    __syncthreads();
    mx = red[0];
    #pragma unroll
    for (int i = 1; i < 8; ++i) mx = fmaxf(mx, red[i]);
    __syncthreads();

    float s = 0.0f;
    #pragma unroll
    for (int i = 0; i < 8; ++i) { v[i] = __expf(v[i] - mx); s += v[i]; }
    #pragma unroll
    for (int o = 16; o > 0; o >>= 1)
        s += __shfl_xor_sync(0xffffffffu, s, o);
    if ((tid & 31) == 0) red[tid >> 5] = s;
    __syncthreads();
    s = 0.0f;
    #pragma unroll
    for (int i = 0; i < 8; ++i) s += red[i];

    const float inv = 1.0f / s;
    #pragma unroll
    for (int i = 0; i < 8; ++i) {
        const float p = v[i] * inv;
        const long long idx = base + tid + 256 * i;
        __nv_bfloat16 h = __float2bfloat16(p);
        Ph[idx] = h;
        Pl[idx] = __float2bfloat16(p - __bfloat162float(h));
    }
}

// ---------------------------------------------------------------------------
// Host
// ---------------------------------------------------------------------------
extern "C" void kernel_launch(void* const* d_in, const int* in_sizes, int n_in,
                              void* d_out, int out_size)
{
    const float* q    = (const float*)d_in[0];
    const float* k    = (const float*)d_in[1];
    const float* v    = (const float*)d_in[2];
    const float* mask = (const float*)d_in[3];
    const float* Wq   = (const float*)d_in[4];
    const float* bq   = (const float*)d_in[5];
    const float* Wk   = (const float*)d_in[6];
    const float* bk   = (const float*)d_in[7];
    const float* Wv   = (const float*)d_in[8];
    const float* bv   = (const float*)d_in[9];
    const float* Wg   = (const float*)d_in[10];
    const float* bg   = (const float*)d_in[11];
    float* out = (float*)d_out;

    #define SYM(p, s) void* p##_; cudaGetSymbolAddress(&p##_, s); \
                      __nv_bfloat16* p = (__nv_bfloat16*)p##_;
    SYM(qh, g_qh)   SYM(ql, g_ql)   SYM(kh, g_kh)   SYM(kl, g_kl)
    SYM(vh, g_vh)   SYM(vl, g_vl)
    SYM(Wqth, g_Wqth) SYM(Wqtl, g_Wqtl) SYM(Wkth, g_Wkth) SYM(Wktl, g_Wktl)
    SYM(Wvth, g_Wvth) SYM(Wvtl, g_Wvtl) SYM(Wgth, g_Wgth) SYM(Wgtl, g_Wgtl)
    SYM(qph, g_qph) SYM(qpl, g_qpl) SYM(kph, g_kph) SYM(kpl, g_kpl)
    SYM(vph, g_vph) SYM(vpl, g_vpl) SYM(vpTh, g_vpTh) SYM(vpTl, g_vpTl)
    SYM(Ph, g_Ph)   SYM(Pl, g_Pl)   SYM(xh, g_xh)   SYM(xl, g_xl)
    #undef SYM
    void* S_; cudaGetSymbolAddress(&S_, g_S); float* S = (float*)S_;

    const int SMEM_DYN = 12 * 16384 + 1024;   // 3-stage x 4 tiles + align pad
    cudaFuncSetAttribute(mma_gemm<0, false>, cudaFuncAttributeMaxDynamicSharedMemorySize, SMEM_DYN);
    cudaFuncSetAttribute(mma_gemm<1, false>, cudaFuncAttributeMaxDynamicSharedMemorySize, SMEM_DYN);
    cudaFuncSetAttribute(mma_gemm<2, true>,  cudaFuncAttributeMaxDynamicSharedMemorySize, SMEM_DYN);

    const long long LD = (long long)LLEN * DDIM;   // 2M
    const long long LLsq = (long long)LLEN * LLEN; // 4M

    // 1) split inputs to bf16 hi/lo
    split_k<<<MTOT * DDIM / 1024, 256>>>(q, qh, ql);
    split_k<<<MTOT * DDIM / 1024, 256>>>(k, kh, kl);
    split_k<<<MTOT * DDIM / 1024, 256>>>(v, vh, vl);

    // 2) transpose + split weights: W[K,N] -> Wt[N,K]
    {
        dim3 b(32, 8);
        transpose_split_k<<<dim3(32, 32), b>>>(Wq, Wqth, Wqtl, DDIM, DDIM);
        transpose_split_k<<<dim3(32, 32), b>>>(Wk, Wkth, Wktl, DDIM, DDIM);
        transpose_split_k<<<dim3(32, 32), b>>>(Wv, Wvth, Wvtl, DDIM, DDIM);
        transpose_split_k<<<dim3(32, 64), b>>>(Wg, Wgth, Wgtl, 2 * DDIM, DDIM);
    }

    // 3) projections: qp/kp/vp = in @ W + b  (M=16384, N=1024, K=1024)
    {
        dim3 g(DDIM / 128, MTOT / 128, 1);
        mma_gemm<0, false><<<g, 256, SMEM_DYN>>>(qh, ql, nullptr, nullptr, DDIM, 0,
            Wqth, Wqtl, DDIM, bq, nullptr, qph, qpl, DDIM, DDIM, 0, 0, 0, 0.f,
            nullptr, nullptr, nullptr, nullptr);
        mma_gemm<0, false><<<g, 256, SMEM_DYN>>>(kh, kl, nullptr, nullptr, DDIM, 0,
            Wkth, Wktl, DDIM, bk, nullptr, kph, kpl, DDIM, DDIM, 0, 0, 0, 0.f,
            nullptr, nullptr, nullptr, nullptr);
        mma_gemm<0, false><<<g, 256, SMEM_DYN>>>(vh, vl, nullptr, nullptr, DDIM, 0,
            Wvth, Wvtl, DDIM, bv, nullptr, vph, vpl, DDIM, DDIM, 0, 0, 0, 0.f,
            nullptr, nullptr, nullptr, nullptr);
    }

    // 4) transpose vp -> vpT [D, M]
    {
        dim3 b(32, 8);
        transpose_bf16_k<<<dim3(32, 512), b>>>(vph, vpTh, MTOT, DDIM);
        transpose_bf16_k<<<dim3(32, 512), b>>>(vpl, vpTl, MTOT, DDIM);
    }

    // 5) scores: S[b] = (qp[b] @ kp[b]^T) / 32  (per batch 2048x2048, K=1024)
    {
        dim3 g(LLEN / 128, LLEN / 128, BB);
        mma_gemm<1, false><<<g, 256, SMEM_DYN>>>(qph, qpl, nullptr, nullptr, DDIM, 0,
            kph, kpl, DDIM, nullptr, S, nullptr, nullptr, LLEN, DDIM,
            LD, LD, LLsq, 0.03125f, nullptr, nullptr, nullptr, nullptr);
    }

    // 6) softmax -> P hi/lo
    softmax_split_k<<<MTOT, 256>>>(S, Ph, Pl);

    // 7) x[b] = P[b] @ vp[b]  (B operand = vpT slice, ldb = MTOT)
    {
        dim3 g(DDIM / 128, LLEN / 128, BB);
        mma_gemm<0, false><<<g, 256, SMEM_DYN>>>(Ph, Pl, nullptr, nullptr, LLEN, 0,
            vpTh, vpTl, MTOT, nullptr, nullptr, xh, xl, DDIM, LLEN,
            LLsq, LLEN, LD, 0.f, nullptr, nullptr, nullptr, nullptr);
    }

    // 8) gate GEMM + fused epilogue -> d_out
    {
        dim3 g(DDIM / 128, MTOT / 128, 1);
        mma_gemm<2, true><<<g, 256, SMEM_DYN>>>(qph, qpl, xh, xl, DDIM, DDIM,
            Wgth, Wgtl, 2 * DDIM, bg, out, nullptr, nullptr, DDIM, 2 * DDIM,
            0, 0, 0, 0.f, xh, xl, q, mask);
    }
}

// round 7
// speedup vs baseline: 7.6023x; 2.7188x over previous
#include <cuda_runtime.h>
#include <cuda_fp16.h>
#include <cstdint>
#include <math.h>

#define BB 8
#define LLEN 2048
#define DDIM 1024
#define MTOT (BB * LLEN)          // 16384

// ---------------------------------------------------------------------------
// Scratch (__device__ globals; allocation-free per harness rules)
// ---------------------------------------------------------------------------
__device__ __half g_q16[MTOT * DDIM], g_k16[MTOT * DDIM], g_v16[MTOT * DDIM];
__device__ __half g_WqT[DDIM * DDIM], g_WkT[DDIM * DDIM], g_WvT[DDIM * DDIM];
__device__ __half g_WgT[DDIM * 2 * DDIM];
__device__ __half g_qp[MTOT * DDIM], g_kp[MTOT * DDIM], g_vp[MTOT * DDIM];
__device__ __half g_vpT[MTOT * DDIM];
__device__ float  g_S[BB * LLEN * LLEN];          // 134 MB
__device__ __half g_P[BB * LLEN * LLEN];          // 67 MB
__device__ __half g_x16[MTOT * DDIM];

// ---------------------------------------------------------------------------
// helpers
// ---------------------------------------------------------------------------
__device__ __forceinline__ uint32_t smem_u32(const void* p) {
    uint32_t a;
    asm("{ .reg .u64 t; cvta.to.shared.u64 t, %1; cvt.u32.u64 %0, t; }"
        : "=r"(a) : "l"(p));
    return a;
}
__device__ __forceinline__ void cp16(uint32_t d, const void* s) {
    asm volatile("cp.async.cg.shared.global [%0], [%1], 16;"
                 :: "r"(d), "l"(s) : "memory");
}
__device__ __forceinline__ void cp_commit() {
    asm volatile("cp.async.commit_group;" ::: "memory");
}
template <int N>
__device__ __forceinline__ void cp_wait() {
    asm volatile("cp.async.wait_group %0;" :: "n"(N) : "memory");
}
__device__ __forceinline__ void ldsm4(uint32_t addr, uint32_t* r) {
    asm volatile("ldmatrix.sync.aligned.m8n8.x4.shared.b16 {%0,%1,%2,%3}, [%4];"
                 : "=r"(r[0]), "=r"(r[1]), "=r"(r[2]), "=r"(r[3]) : "r"(addr));
}
__device__ __forceinline__ void mma16816(float* c, const uint32_t* a,
                                         uint32_t b0, uint32_t b1) {
    asm volatile(
        "mma.sync.aligned.m16n8k16.row.col.f32.f16.f16.f32 "
        "{%0,%1,%2,%3}, {%4,%5,%6,%7}, {%8,%9}, {%0,%1,%2,%3};"
        : "+f"(c[0]), "+f"(c[1]), "+f"(c[2]), "+f"(c[3])
        : "r"(a[0]), "r"(a[1]), "r"(a[2]), "r"(a[3]), "r"(b0), "r"(b1));
}

#define SWZ(o) ((o) ^ (((o) >> 3) & 0x70))

__device__ __forceinline__ uint32_t h2pack(float a, float b) {
    __half2 h = __floats2half2_rn(a, b);
    return *(uint32_t*)&h;
}

// ---------------------------------------------------------------------------
// fp16 HMMA GEMM: C[M,N] = epi( A[M,K] @ B[N,K]^T ), single pass
//   CTA tile 128x128, BK=64, 3-stage cp.async pipeline, 8 warps (32x64 each)
//   2 CTAs/SM (96KB smem each).
//   EPI 0: +bias (nullable), write fp16
//   EPI 1: *alpha, write fp32
//   EPI 2: gate: out = x16*mask*sigmoid(acc+bias) + q0, write fp32
// ---------------------------------------------------------------------------
template <int EPI, bool CONCAT>
__global__ __launch_bounds__(256, 2)
void hgemm(const __half* __restrict__ A, const __half* __restrict__ A2,
           int lda, int KA,
           const __half* __restrict__ B, int ldb,
           const float* __restrict__ bias,
           float* __restrict__ Cf, __half* __restrict__ Ch,
           int ldc, int K,
           long long sA, long long sB, long long sC, float alpha,
           const __half* __restrict__ x16, const float* __restrict__ q0,
           const float* __restrict__ mask)
{
    extern __shared__ char dsm[];
    const uint32_t raw = smem_u32(dsm);
    const uint32_t abase = (raw + 1023u) & ~1023u;

    constexpr int TILE = 16384;                 // one 128x64 fp16 tile (swizzled)
    constexpr int OFF_A = 0;                    // 3 stages
    constexpr int OFF_B = 3 * TILE;

    const int tid = threadIdx.x, wid = tid >> 5, lid = tid & 31;
    const int bn = blockIdx.x, bm = blockIdx.y, bz = blockIdx.z;

    A += (long long)bz * sA;
    B += (long long)bz * sB;
    if (EPI == 1 || EPI == 2) Cf += (long long)bz * sC;
    if (EPI == 0) Ch += (long long)bz * sC;

    const int rowA0 = bm * 128, rowB0 = bn * 128;

    auto stage = [&](int kt, int buf) {
        const int r = tid >> 3, seg = tid & 7;
        long long kc = (long long)kt * 64 + seg * 8;
        const __half* pA = A;
        long long kA = kc;
        if (CONCAT && kc >= KA) { pA = A2; kA = kc - KA; }
        #pragma unroll
        for (int i = 0; i < 4; ++i) {
            const int rr = i * 32 + r;
            const uint32_t so = SWZ(rr * 128 + seg * 16);
            cp16(abase + OFF_A + buf * TILE + so, pA + (long long)(rowA0 + rr) * lda + kA);
            cp16(abase + OFF_B + buf * TILE + so, B + (long long)(rowB0 + rr) * ldb + kc);
        }
    };

    const int wm0 = (wid & 3) * 32;     // warp m offset (4 warps over 128)
    const int wn0 = (wid >> 2) * 64;    // warp n offset (2 warps over 128)
    const int r16 = lid & 15, hseg = lid >> 4;

    float acc[2][8][4] = {};

    const int nt = K / 64;
    stage(0, 0); cp_commit();
    stage(1, 1); cp_commit();

    for (int t = 0; t < nt; ++t) {
        if (t + 1 < nt) cp_wait<1>(); else cp_wait<0>();
        __syncthreads();
        if (t + 2 < nt) { stage(t + 2, (t + 2) % 3); cp_commit(); }

        const int buf = t % 3;
        const uint32_t ba = abase + OFF_A + buf * TILE;
        const uint32_t bb = abase + OFF_B + buf * TILE;

        #pragma unroll
        for (int s = 0; s < 4; ++s) {
            uint32_t a[2][4], b[4][4];
            #pragma unroll
            for (int mf = 0; mf < 2; ++mf) {
                const uint32_t o = (uint32_t)((wm0 + mf * 16 + r16) * 128 + s * 32 + hseg * 16);
                ldsm4(ba + SWZ(o), a[mf]);
            }
            #pragma unroll
            for (int g = 0; g < 4; ++g) {
                const uint32_t o = (uint32_t)((wn0 + g * 16 + r16) * 128 + s * 32 + hseg * 16);
                ldsm4(bb + SWZ(o), b[g]);
            }
            #pragma unroll
            for (int mf = 0; mf < 2; ++mf)
                #pragma unroll
                for (int nf = 0; nf < 8; ++nf) {
                    const int g = nf >> 1, o = nf & 1;
                    mma16816(acc[mf][nf], a[mf], b[g][o], b[g][o + 2]);
                }
        }
        // no trailing barrier: next iteration's cp_wait + barrier provide
        // ordering before any staging buffer is overwritten.
    }

    // ------------------- epilogue -------------------
    #pragma unroll
    for (int mf = 0; mf < 2; ++mf) {
        #pragma unroll
        for (int nf = 0; nf < 8; ++nf) {
            const int col = bn * 128 + wn0 + nf * 8 + (lid & 3) * 2;
            #pragma unroll
            for (int h = 0; h < 2; ++h) {
                const int row = bm * 128 + wm0 + mf * 16 + (lid >> 2) + h * 8;
                const long long off = (long long)row * ldc + col;
                float v0 = acc[mf][nf][h * 2 + 0];
                float v1 = acc[mf][nf][h * 2 + 1];

                if (EPI == 0) {
                    if (bias) {
                        const float2 b2 = *(const float2*)(bias + col);
                        v0 += b2.x; v1 += b2.y;
                    }
                    *(uint32_t*)(Ch + off) = h2pack(v0, v1);
                } else if (EPI == 1) {
                    *(float2*)(Cf + off) = make_float2(v0 * alpha, v1 * alpha);
                } else {
                    const float mv = mask[row];
                    const float2 b2 = *(const float2*)(bias + col);
                    const __half2 xh2 = *(const __half2*)(x16 + off);
                    const float2 xf = __half22float2(xh2);
                    const float2 q2 = *(const float2*)(q0 + off);
                    const float g0 = v0 + b2.x, g1 = v1 + b2.y;
                    const float s0 = 1.0f / (1.0f + __expf(-g0));
                    const float s1 = 1.0f / (1.0f + __expf(-g1));
                    *(float2*)(Cf + off) = make_float2(xf.x * mv * s0 + q2.x,
                                                       xf.y * mv * s1 + q2.y);
                }
            }
        }
    }
}

// ---------------------------------------------------------------------------
// fp32 -> fp16 convert (elementwise, 4/thread)
// ---------------------------------------------------------------------------
__global__ __launch_bounds__(256)
void conv_k(const float* __restrict__ X, __half* __restrict__ H)
{
    const long long i = ((long long)blockIdx.x * 256 + threadIdx.x) * 4;
    float4 v = *(const float4*)(X + i);
    uint2 o;
    o.x = h2pack(v.x, v.y);
    o.y = h2pack(v.z, v.w);
    *(uint2*)(H + i) = o;
}

// W[R,C] fp32 -> T[C,R] fp16 (transpose + convert)
__global__ __launch_bounds__(256)
void transpose_conv_k(const float* __restrict__ W, __half* __restrict__ T,
                      int R, int C)
{
    __shared__ float tile[32][33];
    const int tx = threadIdx.x, ty = threadIdx.y;
    const int x = blockIdx.x * 32 + tx;
    const int y0 = blockIdx.y * 32;
    #pragma unroll
    for (int j = ty; j < 32; j += 8)
        tile[j][tx] = W[(long long)(y0 + j) * C + x];
    __syncthreads();
    const int ox = y0 + tx;
    const int oy0 = blockIdx.x * 32;
    #pragma unroll
    for (int j = ty; j < 32; j += 8)
        T[(long long)(oy0 + j) * R + ox] = __float2half_rn(tile[tx][j]);
}

// fp16 transpose: X[R,C] -> T[C,R]
__global__ __launch_bounds__(256)
void transpose_h_k(const __half* __restrict__ X, __half* __restrict__ T,
                   int R, int C)
{
    __shared__ __half tile[32][34];
    const int tx = threadIdx.x, ty = threadIdx.y;
    const int x = blockIdx.x * 32 + tx;
    const int y0 = blockIdx.y * 32;
    #pragma unroll
    for (int j = ty; j < 32; j += 8)
        tile[j][tx] = X[(long long)(y0 + j) * C + x];
    __syncthreads();
    const int ox = y0 + tx;
    const int oy0 = blockIdx.x * 32;
    #pragma unroll
    for (int j = ty; j < 32; j += 8)
        T[(long long)(oy0 + j) * R + ox] = tile[tx][j];
}

// Row softmax over S (rows of 2048 fp32) -> P fp16
__global__ __launch_bounds__(256)
void softmax_h_k(const float* __restrict__ S, __half* __restrict__ P)
{
    const long long base = (long long)blockIdx.x * LLEN;
    const float* row = S + base;
    const int tid = threadIdx.x;

    float v[8];
    #pragma unroll
    for (int i = 0; i < 8; ++i) v[i] = row[tid + 256 * i];

    float mx = v[0];
    #pragma unroll
    for (int i = 1; i < 8; ++i) mx = fmaxf(mx, v[i]);
    #pragma unroll
    for (int o = 16; o > 0; o >>= 1)
        mx = fmaxf(mx, __shfl_xor_sync(0xffffffffu, mx, o));

    __shared__ float red[8];
    if ((tid & 31) == 0) red[tid >> 5] = mx;
    __syncthreads();
    mx = red[0];
    #pragma unroll
    for (int i = 1; i < 8; ++i) mx = fmaxf(mx, red[i]);
    __syncthreads();

    float s = 0.0f;
    #pragma unroll
    for (int i = 0; i < 8; ++i) { v[i] = __expf(v[i] - mx); s += v[i]; }
    #pragma unroll
    for (int o = 16; o > 0; o >>= 1)
        s += __shfl_xor_sync(0xffffffffu, s, o);
    if ((tid & 31) == 0) red[tid >> 5] = s;
    __syncthreads();
    s = 0.0f;
    #pragma unroll
    for (int i = 0; i < 8; ++i) s += red[i];

    const float inv = 1.0f / s;
    #pragma unroll
    for (int i = 0; i < 8; ++i)
        P[base + tid + 256 * i] = __float2half_rn(v[i] * inv);
}

// ---------------------------------------------------------------------------
// Host
// ---------------------------------------------------------------------------
extern "C" void kernel_launch(void* const* d_in, const int* in_sizes, int n_in,
                              void* d_out, int out_size)
{
    const float* q    = (const float*)d_in[0];
    const float* k    = (const float*)d_in[1];
    const float* v    = (const float*)d_in[2];
    const float* mask = (const float*)d_in[3];
    const float* Wq   = (const float*)d_in[4];
    const float* bq   = (const float*)d_in[5];
    const float* Wk   = (const float*)d_in[6];
    const float* bk   = (const float*)d_in[7];
    const float* Wv   = (const float*)d_in[8];
    const float* bv   = (const float*)d_in[9];
    const float* Wg   = (const float*)d_in[10];
    const float* bg   = (const float*)d_in[11];
    float* out = (float*)d_out;

    #define SYM(p, s) void* p##_; cudaGetSymbolAddress(&p##_, s); \
                      __half* p = (__half*)p##_;
    SYM(q16, g_q16) SYM(k16, g_k16) SYM(v16, g_v16)
    SYM(WqT, g_WqT) SYM(WkT, g_WkT) SYM(WvT, g_WvT) SYM(WgT, g_WgT)
    SYM(qp, g_qp)   SYM(kp, g_kp)   SYM(vp, g_vp)   SYM(vpT, g_vpT)
    SYM(P, g_P)     SYM(x16, g_x16)
    #undef SYM
    void* S_; cudaGetSymbolAddress(&S_, g_S); float* S = (float*)S_;

    const int SMEM_DYN = 6 * 16384 + 1024;   // 3 stages x (A+B) + align pad
    cudaFuncSetAttribute(hgemm<0, false>, cudaFuncAttributeMaxDynamicSharedMemorySize, SMEM_DYN);
    cudaFuncSetAttribute(hgemm<1, false>, cudaFuncAttributeMaxDynamicSharedMemorySize, SMEM_DYN);
    cudaFuncSetAttribute(hgemm<2, true>,  cudaFuncAttributeMaxDynamicSharedMemorySize, SMEM_DYN);

    const long long LD = (long long)LLEN * DDIM;   // 2M
    const long long LLsq = (long long)LLEN * LLEN; // 4M

    // 1) convert inputs to fp16
    conv_k<<<MTOT * DDIM / 1024, 256>>>(q, q16);
    conv_k<<<MTOT * DDIM / 1024, 256>>>(k, k16);
    conv_k<<<MTOT * DDIM / 1024, 256>>>(v, v16);

    // 2) transpose + convert weights: W[K,N] -> Wt[N,K] fp16
    {
        dim3 b(32, 8);
        transpose_conv_k<<<dim3(32, 32), b>>>(Wq, WqT, DDIM, DDIM);
        transpose_conv_k<<<dim3(32, 32), b>>>(Wk, WkT, DDIM, DDIM);
        transpose_conv_k<<<dim3(32, 32), b>>>(Wv, WvT, DDIM, DDIM);
        transpose_conv_k<<<dim3(32, 64), b>>>(Wg, WgT, 2 * DDIM, DDIM);
    }

    // 3) projections: qp/kp/vp = in @ W + b  (M=16384, N=1024, K=1024)
    {
        dim3 g(DDIM / 128, MTOT / 128, 1);
        hgemm<0, false><<<g, 256, SMEM_DYN>>>(q16, nullptr, DDIM, 0, WqT, DDIM,
            bq, nullptr, qp, DDIM, DDIM, 0, 0, 0, 0.f, nullptr, nullptr, nullptr);
        hgemm<0, false><<<g, 256, SMEM_DYN>>>(k16, nullptr, DDIM, 0, WkT, DDIM,
            bk, nullptr, kp, DDIM, DDIM, 0, 0, 0, 0.f, nullptr, nullptr, nullptr);
        hgemm<0, false><<<g, 256, SMEM_DYN>>>(v16, nullptr, DDIM, 0, WvT, DDIM,
            bv, nullptr, vp, DDIM, DDIM, 0, 0, 0, 0.f, nullptr, nullptr, nullptr);
    }

    // 4) transpose vp [MTOT, D] -> vpT [D, MTOT]
    {
        dim3 b(32, 8);
        transpose_h_k<<<dim3(32, 512), b>>>(vp, vpT, MTOT, DDIM);
    }

    // 5) scores: S[b] = (qp[b] @ kp[b]^T) / 32  (per batch 2048x2048, K=1024)
    {
        dim3 g(LLEN / 128, LLEN / 128, BB);
        hgemm<1, false><<<g, 256, SMEM_DYN>>>(qp, nullptr, DDIM, 0, kp, DDIM,
            nullptr, S, nullptr, LLEN, DDIM, LD, LD, LLsq, 0.03125f,
            nullptr, nullptr, nullptr);
    }

    // 6) softmax -> P fp16
    softmax_h_k<<<MTOT, 256>>>(S, P);

    // 7) x[b] = P[b] @ vp[b]  (B operand = vpT slice, ldb = MTOT)
    {
        dim3 g(DDIM / 128, LLEN / 128, BB);
        hgemm<0, false><<<g, 256, SMEM_DYN>>>(P, nullptr, LLEN, 0, vpT, MTOT,
            nullptr, nullptr, x16, DDIM, LLEN, LLsq, LLEN, LD, 0.f,
            nullptr, nullptr, nullptr);
    }

    // 8) gate GEMM + fused epilogue -> d_out
    {
        dim3 g(DDIM / 128, MTOT / 128, 1);
        hgemm<2, true><<<g, 256, SMEM_DYN>>>(qp, x16, DDIM, DDIM, WgT, 2 * DDIM,
            bg, out, nullptr, DDIM, 2 * DDIM, 0, 0, 0, 0.f, x16, q, mask);
    }
}